// round 12
// baseline (speedup 1.0000x reference)
#include <cuda_runtime.h>

#define NP 100000
#define NL 64
#define FP 128
#define FL 64
#define HID 128
#define ED 64
#define EC 1600000
#define EI 100000
#define ER 100000

// ---------------- scratch (device globals; no allocations) -------------------
__device__ int   g_deg[NP];
__device__ float g_dis[NP];
__device__ float g_y[NP * HID];
__device__ float g_z[NP * HID];
__device__ float g_acc[NP * HID];
__device__ float g_xp1[NP * HID];
__device__ float g_r1[NL * HID];
__device__ float g_r2[NL * ED];
__device__ float g_t2[NL * ED];
__device__ float g_xl1[NL * HID];
__device__ float g_aggl1[NL * HID];
__device__ float g_aggl2[NL * HID];

__device__ __forceinline__ int clampi(int v, int hi) {
    return v < 0 ? 0 : (v >= hi ? hi - 1 : v);
}

// ---------------- small utility kernels --------------------------------------
__global__ void k_zero_init(int* deg, float* a1, float* a2) {
    int i = blockIdx.x * blockDim.x + threadIdx.x;
    if (i < NP) deg[i] = 0;
    if (i < NL * HID) { a1[i] = 0.f; a2[i] = 0.f; }
}

__global__ void k_zero_acc(float* acc, int n) {
    int i = blockIdx.x * blockDim.x + threadIdx.x;
    if (i < n) acc[i] = 0.f;
}

__global__ void k_count(const int* __restrict__ dst, int* deg) {
    for (int e = blockIdx.x * blockDim.x + threadIdx.x; e < EC;
         e += gridDim.x * blockDim.x)
        atomicAdd(&deg[clampi(dst[e], NP)], 1);
}

__global__ void k_dis(const int* __restrict__ deg, float* dis) {
    int i = blockIdx.x * blockDim.x + threadIdx.x;
    if (i < NP) dis[i] = rsqrtf((float)(deg[i] + 1));
}

// ---------------- fp32 SGEMM: C[M,N] = A[M,K] @ W[K,N] -----------------------
template <int BM, int BN, int BK, int TM, int TN>
__global__ void sgemm(const float* __restrict__ A, const float* __restrict__ W,
                      float* __restrict__ C, int M, int N, int K) {
    __shared__ float As[BK][BM];
    __shared__ float Bs[BK][BN];
    const int tx = threadIdx.x % (BN / TN);
    const int ty = threadIdx.x / (BN / TN);
    const int m0 = blockIdx.x * BM;
    const int n0 = blockIdx.y * BN;

    float acc[TM][TN];
#pragma unroll
    for (int i = 0; i < TM; i++)
#pragma unroll
        for (int j = 0; j < TN; j++) acc[i][j] = 0.f;

    for (int k0 = 0; k0 < K; k0 += BK) {
#pragma unroll
        for (int u = 0; u < (BM * BK) / (4 * 256); u++) {
            int idx4 = threadIdx.x + u * 256;
            int r = idx4 / (BK / 4);
            int c = (idx4 % (BK / 4)) * 4;
            int gm = m0 + r;
            float4 v = make_float4(0.f, 0.f, 0.f, 0.f);
            if (gm < M) v = *(const float4*)&A[(size_t)gm * K + k0 + c];
            As[c + 0][r] = v.x;
            As[c + 1][r] = v.y;
            As[c + 2][r] = v.z;
            As[c + 3][r] = v.w;
        }
        {
            int r = threadIdx.x / (BN / 4);
            int c = (threadIdx.x % (BN / 4)) * 4;
            float4 v = *(const float4*)&W[(size_t)(k0 + r) * N + n0 + c];
            *(float4*)&Bs[r][c] = v;
        }
        __syncthreads();
#pragma unroll
        for (int k = 0; k < BK; k++) {
            float4 a0 = *(const float4*)&As[k][ty * TM];
            float4 a1 = *(const float4*)&As[k][ty * TM + 4];
            float4 b0 = *(const float4*)&Bs[k][tx * TN];
            float ra[TM] = {a0.x, a0.y, a0.z, a0.w, a1.x, a1.y, a1.z, a1.w};
            float rb[TN] = {b0.x, b0.y, b0.z, b0.w};
#pragma unroll
            for (int i = 0; i < TM; i++)
#pragma unroll
                for (int j = 0; j < TN; j++) acc[i][j] += ra[i] * rb[j];
        }
        __syncthreads();
    }
#pragma unroll
    for (int i = 0; i < TM; i++) {
        int gm = m0 + ty * TM + i;
        if (gm < M) {
            float4 v = make_float4(acc[i][0], acc[i][1], acc[i][2], acc[i][3]);
            *(float4*)&C[(size_t)gm * N + n0 + tx * TN] = v;
        }
    }
}

// ---------------- tiny GEMM: r1 = xl @ W1rr  (64x64 @ 64x128) ----------------
__global__ void k_r1(const float* __restrict__ xl, const float* __restrict__ W,
                     float* __restrict__ r1) {
    int o = blockIdx.x * blockDim.x + threadIdx.x;
    if (o >= NL * HID) return;
    int i = o >> 7, j = o & 127;
    float acc = 0.f;
    for (int k = 0; k < FL; k++) acc += __ldg(&xl[i * FL + k]) * __ldg(&W[k * HID + j]);
    r1[o] = acc;
}

// ---------------- cites scatter: acc[dst] += dis[src]*y[src] -----------------
template <int C>
__global__ void k_cites(const int* __restrict__ src, const int* __restrict__ dst,
                        const float* __restrict__ dis,
                        const float* __restrict__ Y, float* __restrict__ A) {
    int gw = (blockIdx.x * blockDim.x + threadIdx.x) >> 5;
    int lane = threadIdx.x & 31;
    int nw = (gridDim.x * blockDim.x) >> 5;
    for (int e = gw; e < EC; e += nw) {
        int s = clampi(src[e], NP), d = clampi(dst[e], NP);
        float ws = dis[s];
        if (C == 128) {
            float4 v = ((const float4*)Y)[(size_t)s * 32 + lane];
            float* p = A + (size_t)d * 128 + lane * 4;
            atomicAdd(p + 0, ws * v.x);
            atomicAdd(p + 1, ws * v.y);
            atomicAdd(p + 2, ws * v.z);
            atomicAdd(p + 3, ws * v.w);
        } else {
            float2 v = ((const float2*)Y)[(size_t)s * 32 + lane];
            float* p = A + (size_t)d * 64 + lane * 2;
            atomicAdd(p + 0, ws * v.x);
            atomicAdd(p + 1, ws * v.y);
        }
    }
}

// ---------------- rev scatter: Z[dst] += R[src] (R over NL rows) -------------
template <int C>
__global__ void k_rev(const float* __restrict__ R, const int* __restrict__ src,
                      const int* __restrict__ dst, float* __restrict__ Z) {
    int gw = (blockIdx.x * blockDim.x + threadIdx.x) >> 5;
    int lane = threadIdx.x & 31;
    int nw = (gridDim.x * blockDim.x) >> 5;
    for (int e = gw; e < ER; e += nw) {
        int s = clampi(src[e], NL), d = clampi(dst[e], NP);
        if (C == 128) {
            float4 v = ((const float4*)R)[s * 32 + lane];
            float* p = Z + (size_t)d * 128 + lane * 4;
            atomicAdd(p + 0, v.x);
            atomicAdd(p + 1, v.y);
            atomicAdd(p + 2, v.z);
            atomicAdd(p + 3, v.w);
        } else {
            float2 v = ((const float2*)R)[s * 32 + lane];
            float* p = Z + (size_t)d * 64 + lane * 2;
            atomicAdd(p + 0, v.x);
            atomicAdd(p + 1, v.y);
        }
    }
}

// ---------------- is scatter: G[dst] += X[src] (128 cols) --------------------
__global__ void k_is(const float* __restrict__ X, const int* __restrict__ src,
                     const int* __restrict__ dst, float* __restrict__ G) {
    int gw = (blockIdx.x * blockDim.x + threadIdx.x) >> 5;
    int lane = threadIdx.x & 31;
    int nw = (gridDim.x * blockDim.x) >> 5;
    for (int e = gw; e < EI; e += nw) {
        int s = clampi(src[e], NP), d = clampi(dst[e], NL);
        float4 v = ((const float4*)X)[(size_t)s * 32 + lane];
        float* p = G + (size_t)d * 128 + lane * 4;
        atomicAdd(p + 0, v.x);
        atomicAdd(p + 1, v.y);
        atomicAdd(p + 2, v.z);
        atomicAdd(p + 3, v.w);
    }
}

// ---------------- epilogue layer 1: xp1 = relu(0.5*(...)) --------------------
__global__ void k_ep1(const float* __restrict__ dis, const float* __restrict__ acc,
                      const float* __restrict__ y, const float* __restrict__ z,
                      const float* __restrict__ b1g, const float* __restrict__ b1r,
                      float* __restrict__ xp1) {
    int i = blockIdx.x * blockDim.x + threadIdx.x;
    if (i >= NP * HID) return;
    int row = i >> 7, col = i & 127;
    float di = dis[row];
    float v = 0.5f * (di * acc[i] + di * di * y[i] + b1g[col] + z[i] + b1r[col]);
    xp1[i] = fmaxf(v, 0.f);
}

// ---------------- epilogue layer 2: out_p = 0.5*(...) ------------------------
__global__ void k_ep2(const float* __restrict__ dis, const float* __restrict__ acc,
                      const float* __restrict__ y, const float* __restrict__ z,
                      const float* __restrict__ b2g, const float* __restrict__ b2r,
                      float* __restrict__ out) {
    int i = blockIdx.x * blockDim.x + threadIdx.x;
    if (i >= NP * ED) return;
    int row = i >> 6, col = i & 63;
    float di = dis[row];
    float v = 0.5f * (di * acc[i] + di * di * y[i] + b2g[col] + z[i] + b2r[col]);
    out[i] = v;
}

// ---------------- label layer 1: xl1 = relu(aggl1@W1ri + xl@W1oi + b1i) ------
__global__ void k_label1a(const float* __restrict__ aggl1, const float* __restrict__ xl,
                          const float* __restrict__ W1ri, const float* __restrict__ W1oi,
                          const float* __restrict__ b1i, float* __restrict__ xl1) {
    int o = blockIdx.x * blockDim.x + threadIdx.x;
    if (o >= NL * HID) return;
    int i = o >> 7, j = o & 127;
    float acc = __ldg(&b1i[j]);
    for (int k = 0; k < HID; k++)
        acc += aggl1[i * HID + k] * __ldg(&W1ri[k * HID + j]);
    for (int k = 0; k < FL; k++)
        acc += __ldg(&xl[i * FL + k]) * __ldg(&W1oi[k * HID + j]);
    xl1[o] = fmaxf(acc, 0.f);
}

// ---------------- label pre-transforms: r2 = xl1@W2rr, t2 = xl1@W2oi + b2i ---
__global__ void k_label1b(const float* __restrict__ xl1, const float* __restrict__ W2rr,
                          const float* __restrict__ W2oi, const float* __restrict__ b2i,
                          float* __restrict__ r2, float* __restrict__ t2) {
    int o = blockIdx.x * blockDim.x + threadIdx.x;
    if (o >= NL * ED) return;
    int i = o >> 6, j = o & 63;
    float a1 = 0.f, a2 = __ldg(&b2i[j]);
    for (int k = 0; k < HID; k++) {
        float xv = xl1[i * HID + k];
        a1 += xv * __ldg(&W2rr[k * ED + j]);
        a2 += xv * __ldg(&W2oi[k * ED + j]);
    }
    r2[o] = a1;
    t2[o] = a2;
}

// ---------------- label layer 2: out_l = aggl2@W2ri + t2 ---------------------
__global__ void k_label2(const float* __restrict__ aggl2, const float* __restrict__ t2,
                         const float* __restrict__ W2ri, float* __restrict__ out) {
    int o = blockIdx.x * blockDim.x + threadIdx.x;
    if (o >= NL * ED) return;
    int i = o >> 6, j = o & 63;
    float acc = t2[o];
    for (int k = 0; k < HID; k++)
        acc += aggl2[i * HID + k] * __ldg(&W2ri[k * ED + j]);
    out[o] = acc;
}

// ---------------- launch -----------------------------------------------------
static const long long SIG_INS[24] = {
    12800000, 4096, 16384, 128, 16384, 8192, 128, 8192, 16384, 128,
    8192, 64, 8192, 8192, 64, 8192, 8192, 64,
    1600000, 1600000, 100000, 100000, 100000, 100000};
static const long long SIG_ALPHA[24] = {
    16384, 8192, 16384, 16384, 8192, 8192, 8192, 8192, 8192, 8192,
    128, 128, 128, 64, 64, 64,
    1600000, 1600000, 100000, 100000, 100000, 100000, 4096, 12800000};
static const int MAP_ALPHA[24] = {
    23, 22, 0, 10, 3, 1, 11, 4, 2, 12, 5, 13, 8, 6, 14, 9, 7, 15,
    17, 16, 19, 18, 21, 20};

static bool sig_match(const int* sz, const long long* sig, long long scale) {
    for (int i = 0; i < 24; i++)
        if ((long long)sz[i] != sig[i] * scale) return false;
    return true;
}

// Resolved device addresses of all scratch symbols. Passing __device__ symbols
// directly as host-side kernel args binds the host shadow copy; on GB300 the
// ATS/C2C path makes that address silently "valid", so scratch writes landed
// in host memory while device reads saw zeros. cudaGetSymbolAddress gives the
// real device addresses (host API, capture-safe, no stream work).
struct Scratch {
    int* deg; float *dis, *y, *z, *acc, *xp1, *r1, *r2, *t2, *xl1, *aggl1, *aggl2;
};
static Scratch P = {};

static void resolve_scratch() {
    if (P.deg) return;
    cudaGetSymbolAddress((void**)&P.deg,   g_deg);
    cudaGetSymbolAddress((void**)&P.dis,   g_dis);
    cudaGetSymbolAddress((void**)&P.y,     g_y);
    cudaGetSymbolAddress((void**)&P.z,     g_z);
    cudaGetSymbolAddress((void**)&P.acc,   g_acc);
    cudaGetSymbolAddress((void**)&P.xp1,   g_xp1);
    cudaGetSymbolAddress((void**)&P.r1,    g_r1);
    cudaGetSymbolAddress((void**)&P.r2,    g_r2);
    cudaGetSymbolAddress((void**)&P.t2,    g_t2);
    cudaGetSymbolAddress((void**)&P.xl1,   g_xl1);
    cudaGetSymbolAddress((void**)&P.aggl1, g_aggl1);
    cudaGetSymbolAddress((void**)&P.aggl2, g_aggl2);
}

extern "C" void kernel_launch(void* const* d_in, const int* in_sizes, int n_in,
                              void* d_out, int out_size) {
    resolve_scratch();

    int map[24];
    for (int i = 0; i < 24; i++) map[i] = i; // default: insertion order
    if (n_in >= 24) {
        if (sig_match(in_sizes, SIG_INS, 1) || sig_match(in_sizes, SIG_INS, 4)) {
            // identity
        } else if (sig_match(in_sizes, SIG_ALPHA, 1) ||
                   sig_match(in_sizes, SIG_ALPHA, 4)) {
            for (int i = 0; i < 24; i++) map[i] = MAP_ALPHA[i];
        } else if (in_sizes[23] == 12800000 || in_sizes[23] == 51200000) {
            for (int i = 0; i < 24; i++) map[i] = MAP_ALPHA[i];
        }
    }

    const float* xp   = (const float*)d_in[map[0]];
    const float* xl   = (const float*)d_in[map[1]];
    const float* W1g  = (const float*)d_in[map[2]];
    const float* b1g  = (const float*)d_in[map[3]];
    const float* W1ri = (const float*)d_in[map[4]];
    const float* W1oi = (const float*)d_in[map[5]];
    const float* b1i  = (const float*)d_in[map[6]];
    const float* W1rr = (const float*)d_in[map[7]];
    const float* W1or = (const float*)d_in[map[8]];
    const float* b1r  = (const float*)d_in[map[9]];
    const float* W2g  = (const float*)d_in[map[10]];
    const float* b2g  = (const float*)d_in[map[11]];
    const float* W2ri = (const float*)d_in[map[12]];
    const float* W2oi = (const float*)d_in[map[13]];
    const float* b2i  = (const float*)d_in[map[14]];
    const float* W2rr = (const float*)d_in[map[15]];
    const float* W2or = (const float*)d_in[map[16]];
    const float* b2r  = (const float*)d_in[map[17]];
    const int* csrc = (const int*)d_in[map[18]];
    const int* cdst = (const int*)d_in[map[19]];
    const int* isrc = (const int*)d_in[map[20]];
    const int* idst = (const int*)d_in[map[21]];
    const int* rsrc = (const int*)d_in[map[22]];
    const int* rdst = (const int*)d_in[map[23]];
    float* out = (float*)d_out;

    // ---- graph prep ----
    k_zero_init<<<(NP + 255) / 256, 256>>>(P.deg, P.aggl1, P.aggl2);
    k_count<<<2048, 256>>>(cdst, P.deg);
    k_dis<<<(NP + 255) / 256, 256>>>(P.deg, P.dis);

    // ---- layer 1, paper side ----
    sgemm<128, 64, 16, 8, 4><<<dim3(782, 2), 256>>>(xp, W1g, P.y, NP, HID, FP);
    sgemm<128, 64, 16, 8, 4><<<dim3(782, 2), 256>>>(xp, W1or, P.z, NP, HID, FP);
    k_r1<<<(NL * HID + 255) / 256, 256>>>(xl, W1rr, P.r1);
    k_rev<128><<<1024, 256>>>(P.r1, rsrc, rdst, P.z);
    k_zero_acc<<<(NP * HID + 255) / 256, 256>>>(P.acc, NP * HID);
    k_cites<128><<<4096, 256>>>(csrc, cdst, P.dis, P.y, P.acc);
    k_ep1<<<(NP * HID + 255) / 256, 256>>>(P.dis, P.acc, P.y, P.z, b1g, b1r, P.xp1);

    // ---- layer 1, label side ----
    k_is<<<1024, 256>>>(xp, isrc, idst, P.aggl1);
    k_label1a<<<(NL * HID + 255) / 256, 256>>>(P.aggl1, xl, W1ri, W1oi, b1i, P.xl1);
    k_label1b<<<(NL * ED + 255) / 256, 256>>>(P.xl1, W2rr, W2oi, b2i, P.r2, P.t2);

    // ---- layer 2, paper side ----
    sgemm<128, 64, 16, 8, 4><<<dim3(782, 1), 256>>>(P.xp1, W2g, P.y, NP, ED, HID);
    sgemm<128, 64, 16, 8, 4><<<dim3(782, 1), 256>>>(P.xp1, W2or, P.z, NP, ED, HID);
    k_rev<64><<<1024, 256>>>(P.r2, rsrc, rdst, P.z);
    k_zero_acc<<<(NP * ED + 255) / 256, 256>>>(P.acc, NP * ED);
    k_cites<64><<<4096, 256>>>(csrc, cdst, P.dis, P.y, P.acc);
    k_ep2<<<(NP * ED + 255) / 256, 256>>>(P.dis, P.acc, P.y, P.z, b2g, b2r, out);

    // ---- layer 2, label side ----
    k_is<<<1024, 256>>>(P.xp1, isrc, idst, P.aggl2);
    if (out_size >= NP * ED + NL * ED)
        k_label2<<<(NL * ED + 255) / 256, 256>>>(P.aggl2, P.t2, W2ri, out + (size_t)NP * ED);
}

// round 14
// speedup vs baseline: 1.7228x; 1.7228x over previous
#include <cuda_runtime.h>

#define NP 100000
#define NL 64
#define FP 128
#define FL 64
#define HID 128
#define ED 64
#define EC 1600000
#define EI 100000
#define ER 100000

// ---------------- scratch (device globals; no allocations) -------------------
__device__ int   g_deg[NP];
__device__ int   g_cursor[NP];
__device__ int   g_rowptr[NP + 1];
__device__ int   g_col[EC];
__device__ int   g_bsum[128];
__device__ float g_dis[NP];
__device__ float g_y[NP * HID];
__device__ float g_z[NP * HID];
__device__ float g_xp1[NP * HID];
__device__ float g_r1[NL * HID];
__device__ float g_r2[NL * ED];
__device__ float g_t2[NL * ED];
__device__ float g_xl1[NL * HID];
__device__ float g_aggl1[NL * HID];
__device__ float g_aggl2[NL * HID];

__device__ __forceinline__ int clampi(int v, int hi) {
    return v < 0 ? 0 : (v >= hi ? hi - 1 : v);
}

// ---------------- init / degree / dis ----------------------------------------
__global__ void k_zero_init(int* deg, int* cursor, float* a1, float* a2) {
    int i = blockIdx.x * blockDim.x + threadIdx.x;
    if (i < NP) { deg[i] = 0; cursor[i] = 0; }
    if (i < NL * HID) { a1[i] = 0.f; a2[i] = 0.f; }
}

__global__ void k_count(const int* __restrict__ dst, int* deg) {
    for (int e = blockIdx.x * blockDim.x + threadIdx.x; e < EC;
         e += gridDim.x * blockDim.x)
        atomicAdd(&deg[clampi(dst[e], NP)], 1);
}

__global__ void k_dis(const int* __restrict__ deg, float* dis) {
    int i = blockIdx.x * blockDim.x + threadIdx.x;
    if (i < NP) dis[i] = rsqrtf((float)(deg[i] + 1));
}

// ---------------- exclusive scan of degrees -> rowptr -------------------------
__global__ void k_scan1(const int* __restrict__ deg, int* rowptr, int* bsum) {
    __shared__ int s[1024];
    int t = threadIdx.x;
    int idx = blockIdx.x * 1024 + t;
    int v = (idx < NP) ? deg[idx] : 0;
    s[t] = v;
    __syncthreads();
    for (int off = 1; off < 1024; off <<= 1) {
        int x = (t >= off) ? s[t - off] : 0;
        __syncthreads();
        s[t] += x;
        __syncthreads();
    }
    if (idx < NP) rowptr[idx + 1] = s[t];
    if (t == 1023) bsum[blockIdx.x] = s[1023];
}

__global__ void k_scan2(int* bsum, int nb) {
    if (threadIdx.x == 0 && blockIdx.x == 0) {
        int run = 0;
        for (int b = 0; b < nb; b++) { int x = bsum[b]; bsum[b] = run; run += x; }
    }
}

__global__ void k_scan3(int* rowptr, const int* __restrict__ bsum) {
    int t = threadIdx.x;
    int idx = blockIdx.x * 1024 + t;
    if (idx < NP) rowptr[idx + 1] += bsum[blockIdx.x];
    if (idx == 0) rowptr[0] = 0;
}

__global__ void k_fill(const int* __restrict__ src, const int* __restrict__ dst,
                       const int* __restrict__ rowptr, int* cursor, int* col) {
    for (int e = blockIdx.x * blockDim.x + threadIdx.x; e < EC;
         e += gridDim.x * blockDim.x) {
        int d = clampi(dst[e], NP);
        int p = atomicAdd(&cursor[d], 1);
        col[clampi(rowptr[d] + p, EC)] = clampi(src[e], NP);
    }
}

// ---------------- fp32 SGEMM: C[M,N] = A[M,K] @ W[K,N] -----------------------
template <int BM, int BN, int BK, int TM, int TN>
__global__ void sgemm(const float* __restrict__ A, const float* __restrict__ W,
                      float* __restrict__ C, int M, int N, int K) {
    __shared__ float As[BK][BM];
    __shared__ float Bs[BK][BN];
    const int tx = threadIdx.x % (BN / TN);
    const int ty = threadIdx.x / (BN / TN);
    const int m0 = blockIdx.x * BM;
    const int n0 = blockIdx.y * BN;

    float acc[TM][TN];
#pragma unroll
    for (int i = 0; i < TM; i++)
#pragma unroll
        for (int j = 0; j < TN; j++) acc[i][j] = 0.f;

    for (int k0 = 0; k0 < K; k0 += BK) {
#pragma unroll
        for (int u = 0; u < (BM * BK) / (4 * 256); u++) {
            int idx4 = threadIdx.x + u * 256;
            int r = idx4 / (BK / 4);
            int c = (idx4 % (BK / 4)) * 4;
            int gm = m0 + r;
            float4 v = make_float4(0.f, 0.f, 0.f, 0.f);
            if (gm < M) v = *(const float4*)&A[(size_t)gm * K + k0 + c];
            As[c + 0][r] = v.x;
            As[c + 1][r] = v.y;
            As[c + 2][r] = v.z;
            As[c + 3][r] = v.w;
        }
        {
            int r = threadIdx.x / (BN / 4);
            int c = (threadIdx.x % (BN / 4)) * 4;
            float4 v = *(const float4*)&W[(size_t)(k0 + r) * N + n0 + c];
            *(float4*)&Bs[r][c] = v;
        }
        __syncthreads();
#pragma unroll
        for (int k = 0; k < BK; k++) {
            float4 a0 = *(const float4*)&As[k][ty * TM];
            float4 a1 = *(const float4*)&As[k][ty * TM + 4];
            float4 b0 = *(const float4*)&Bs[k][tx * TN];
            float ra[TM] = {a0.x, a0.y, a0.z, a0.w, a1.x, a1.y, a1.z, a1.w};
            float rb[TN] = {b0.x, b0.y, b0.z, b0.w};
#pragma unroll
            for (int i = 0; i < TM; i++)
#pragma unroll
                for (int j = 0; j < TN; j++) acc[i][j] += ra[i] * rb[j];
        }
        __syncthreads();
    }
#pragma unroll
    for (int i = 0; i < TM; i++) {
        int gm = m0 + ty * TM + i;
        if (gm < M) {
            float4 v = make_float4(acc[i][0], acc[i][1], acc[i][2], acc[i][3]);
            *(float4*)&C[(size_t)gm * N + n0 + tx * TN] = v;
        }
    }
}

// ---------------- tiny GEMM: r1 = xl @ W1rr  (64x64 @ 64x128) ----------------
__global__ void k_r1(const float* __restrict__ xl, const float* __restrict__ W,
                     float* __restrict__ r1) {
    int o = blockIdx.x * blockDim.x + threadIdx.x;
    if (o >= NL * HID) return;
    int i = o >> 7, j = o & 127;
    float acc = 0.f;
    for (int k = 0; k < FL; k++) acc += __ldg(&xl[i * FL + k]) * __ldg(&W[k * HID + j]);
    r1[o] = acc;
}

// ---------------- rev scatter: Z[dst] += R[src] (R over NL rows) -------------
template <int C>
__global__ void k_rev(const float* __restrict__ R, const int* __restrict__ src,
                      const int* __restrict__ dst, float* __restrict__ Z) {
    int gw = (blockIdx.x * blockDim.x + threadIdx.x) >> 5;
    int lane = threadIdx.x & 31;
    int nw = (gridDim.x * blockDim.x) >> 5;
    for (int e = gw; e < ER; e += nw) {
        int s = clampi(src[e], NL), d = clampi(dst[e], NP);
        if (C == 128) {
            float4 v = ((const float4*)R)[s * 32 + lane];
            float* p = Z + (size_t)d * 128 + lane * 4;
            atomicAdd(p + 0, v.x);
            atomicAdd(p + 1, v.y);
            atomicAdd(p + 2, v.z);
            atomicAdd(p + 3, v.w);
        } else {
            float2 v = ((const float2*)R)[s * 32 + lane];
            float* p = Z + (size_t)d * 64 + lane * 2;
            atomicAdd(p + 0, v.x);
            atomicAdd(p + 1, v.y);
        }
    }
}

// ---------------- is scatter: G[dst] += X[src] (128 cols) --------------------
__global__ void k_is(const float* __restrict__ X, const int* __restrict__ src,
                     const int* __restrict__ dst, float* __restrict__ G) {
    int gw = (blockIdx.x * blockDim.x + threadIdx.x) >> 5;
    int lane = threadIdx.x & 31;
    int nw = (gridDim.x * blockDim.x) >> 5;
    for (int e = gw; e < EI; e += nw) {
        int s = clampi(src[e], NP), d = clampi(dst[e], NL);
        float4 v = ((const float4*)X)[(size_t)s * 32 + lane];
        float* p = G + (size_t)d * 128 + lane * 4;
        atomicAdd(p + 0, v.x);
        atomicAdd(p + 1, v.y);
        atomicAdd(p + 2, v.z);
        atomicAdd(p + 3, v.w);
    }
}

// ---------------- cites CSR-gather + fused epilogue (layer 1, 128 cols) ------
// one warp per paper row: acc = sum_s dis[s]*y[s]; out = relu(0.5*(di*acc +
// di^2*y + b1g + z + b1r))
__global__ void k_final1(const int* __restrict__ rowptr, const int* __restrict__ col,
                         const float* __restrict__ dis, const float* __restrict__ y,
                         const float* __restrict__ z,
                         const float* __restrict__ b1g, const float* __restrict__ b1r,
                         float* __restrict__ xp1) {
    int w = (blockIdx.x * blockDim.x + threadIdx.x) >> 5;
    if (w >= NP) return;
    int lane = threadIdx.x & 31;
    int beg = rowptr[w], end = rowptr[w + 1];
    const float4* y4 = (const float4*)y;
    float4 acc = make_float4(0.f, 0.f, 0.f, 0.f);
    for (int e = beg; e < end; e++) {
        int s = col[e];
        float ws = dis[s];
        float4 v = y4[(size_t)s * 32 + lane];
        acc.x += ws * v.x; acc.y += ws * v.y; acc.z += ws * v.z; acc.w += ws * v.w;
    }
    float di = dis[w], d2 = di * di;
    float4 yv = y4[(size_t)w * 32 + lane];
    float4 zv = ((const float4*)z)[(size_t)w * 32 + lane];
    float4 bg = ((const float4*)b1g)[lane];
    float4 br = ((const float4*)b1r)[lane];
    float4 o;
    o.x = fmaxf(0.5f * (di * acc.x + d2 * yv.x + bg.x + zv.x + br.x), 0.f);
    o.y = fmaxf(0.5f * (di * acc.y + d2 * yv.y + bg.y + zv.y + br.y), 0.f);
    o.z = fmaxf(0.5f * (di * acc.z + d2 * yv.z + bg.z + zv.z + br.z), 0.f);
    o.w = fmaxf(0.5f * (di * acc.w + d2 * yv.w + bg.w + zv.w + br.w), 0.f);
    ((float4*)xp1)[(size_t)w * 32 + lane] = o;
}

// ---------------- cites CSR-gather + fused epilogue (layer 2, 64 cols) -------
__global__ void k_final2(const int* __restrict__ rowptr, const int* __restrict__ col,
                         const float* __restrict__ dis, const float* __restrict__ y,
                         const float* __restrict__ z,
                         const float* __restrict__ b2g, const float* __restrict__ b2r,
                         float* __restrict__ out) {
    int w = (blockIdx.x * blockDim.x + threadIdx.x) >> 5;
    if (w >= NP) return;
    int lane = threadIdx.x & 31;
    int beg = rowptr[w], end = rowptr[w + 1];
    const float2* y2 = (const float2*)y;
    float2 acc = make_float2(0.f, 0.f);
    for (int e = beg; e < end; e++) {
        int s = col[e];
        float ws = dis[s];
        float2 v = y2[(size_t)s * 32 + lane];
        acc.x += ws * v.x; acc.y += ws * v.y;
    }
    float di = dis[w], d2 = di * di;
    float2 yv = y2[(size_t)w * 32 + lane];
    float2 zv = ((const float2*)z)[(size_t)w * 32 + lane];
    float2 bg = ((const float2*)b2g)[lane];
    float2 br = ((const float2*)b2r)[lane];
    float2 o;
    o.x = 0.5f * (di * acc.x + d2 * yv.x + bg.x + zv.x + br.x);
    o.y = 0.5f * (di * acc.y + d2 * yv.y + bg.y + zv.y + br.y);
    ((float2*)out)[(size_t)w * 32 + lane] = o;
}

// ---------------- label layer 1: xl1 = relu(aggl1@W1ri + xl@W1oi + b1i) ------
__global__ void k_label1a(const float* __restrict__ aggl1, const float* __restrict__ xl,
                          const float* __restrict__ W1ri, const float* __restrict__ W1oi,
                          const float* __restrict__ b1i, float* __restrict__ xl1) {
    int o = blockIdx.x * blockDim.x + threadIdx.x;
    if (o >= NL * HID) return;
    int i = o >> 7, j = o & 127;
    float acc = __ldg(&b1i[j]);
    for (int k = 0; k < HID; k++)
        acc += aggl1[i * HID + k] * __ldg(&W1ri[k * HID + j]);
    for (int k = 0; k < FL; k++)
        acc += __ldg(&xl[i * FL + k]) * __ldg(&W1oi[k * HID + j]);
    xl1[o] = fmaxf(acc, 0.f);
}

// ---------------- label pre-transforms: r2 = xl1@W2rr, t2 = xl1@W2oi + b2i ---
__global__ void k_label1b(const float* __restrict__ xl1, const float* __restrict__ W2rr,
                          const float* __restrict__ W2oi, const float* __restrict__ b2i,
                          float* __restrict__ r2, float* __restrict__ t2) {
    int o = blockIdx.x * blockDim.x + threadIdx.x;
    if (o >= NL * ED) return;
    int i = o >> 6, j = o & 63;
    float a1 = 0.f, a2 = __ldg(&b2i[j]);
    for (int k = 0; k < HID; k++) {
        float xv = xl1[i * HID + k];
        a1 += xv * __ldg(&W2rr[k * ED + j]);
        a2 += xv * __ldg(&W2oi[k * ED + j]);
    }
    r2[o] = a1;
    t2[o] = a2;
}

// ---------------- label layer 2: out_l = aggl2@W2ri + t2 ---------------------
__global__ void k_label2(const float* __restrict__ aggl2, const float* __restrict__ t2,
                         const float* __restrict__ W2ri, float* __restrict__ out) {
    int o = blockIdx.x * blockDim.x + threadIdx.x;
    if (o >= NL * ED) return;
    int i = o >> 6, j = o & 63;
    float acc = t2[o];
    for (int k = 0; k < HID; k++)
        acc += aggl2[i * HID + k] * __ldg(&W2ri[k * ED + j]);
    out[o] = acc;
}

// ---------------- launch -----------------------------------------------------
static const long long SIG_INS[24] = {
    12800000, 4096, 16384, 128, 16384, 8192, 128, 8192, 16384, 128,
    8192, 64, 8192, 8192, 64, 8192, 8192, 64,
    1600000, 1600000, 100000, 100000, 100000, 100000};
static const long long SIG_ALPHA[24] = {
    16384, 8192, 16384, 16384, 8192, 8192, 8192, 8192, 8192, 8192,
    128, 128, 128, 64, 64, 64,
    1600000, 1600000, 100000, 100000, 100000, 100000, 4096, 12800000};
static const int MAP_ALPHA[24] = {
    23, 22, 0, 10, 3, 1, 11, 4, 2, 12, 5, 13, 8, 6, 14, 9, 7, 15,
    17, 16, 19, 18, 21, 20};

static bool sig_match(const int* sz, const long long* sig, long long scale) {
    for (int i = 0; i < 24; i++)
        if ((long long)sz[i] != sig[i] * scale) return false;
    return true;
}

struct Scratch {
    int *deg, *cursor, *rowptr, *col, *bsum;
    float *dis, *y, *z, *xp1, *r1, *r2, *t2, *xl1, *aggl1, *aggl2;
};
static Scratch P = {};

static void resolve_scratch() {
    if (P.deg) return;
    cudaGetSymbolAddress((void**)&P.deg,    g_deg);
    cudaGetSymbolAddress((void**)&P.cursor, g_cursor);
    cudaGetSymbolAddress((void**)&P.rowptr, g_rowptr);
    cudaGetSymbolAddress((void**)&P.col,    g_col);
    cudaGetSymbolAddress((void**)&P.bsum,   g_bsum);
    cudaGetSymbolAddress((void**)&P.dis,    g_dis);
    cudaGetSymbolAddress((void**)&P.y,      g_y);
    cudaGetSymbolAddress((void**)&P.z,      g_z);
    cudaGetSymbolAddress((void**)&P.xp1,    g_xp1);
    cudaGetSymbolAddress((void**)&P.r1,     g_r1);
    cudaGetSymbolAddress((void**)&P.r2,     g_r2);
    cudaGetSymbolAddress((void**)&P.t2,     g_t2);
    cudaGetSymbolAddress((void**)&P.xl1,    g_xl1);
    cudaGetSymbolAddress((void**)&P.aggl1,  g_aggl1);
    cudaGetSymbolAddress((void**)&P.aggl2,  g_aggl2);
}

extern "C" void kernel_launch(void* const* d_in, const int* in_sizes, int n_in,
                              void* d_out, int out_size) {
    resolve_scratch();

    int map[24];
    for (int i = 0; i < 24; i++) map[i] = i;
    if (n_in >= 24) {
        if (sig_match(in_sizes, SIG_INS, 1) || sig_match(in_sizes, SIG_INS, 4)) {
        } else if (sig_match(in_sizes, SIG_ALPHA, 1) ||
                   sig_match(in_sizes, SIG_ALPHA, 4)) {
            for (int i = 0; i < 24; i++) map[i] = MAP_ALPHA[i];
        } else if (in_sizes[23] == 12800000 || in_sizes[23] == 51200000) {
            for (int i = 0; i < 24; i++) map[i] = MAP_ALPHA[i];
        }
    }

    const float* xp   = (const float*)d_in[map[0]];
    const float* xl   = (const float*)d_in[map[1]];
    const float* W1g  = (const float*)d_in[map[2]];
    const float* b1g  = (const float*)d_in[map[3]];
    const float* W1ri = (const float*)d_in[map[4]];
    const float* W1oi = (const float*)d_in[map[5]];
    const float* b1i  = (const float*)d_in[map[6]];
    const float* W1rr = (const float*)d_in[map[7]];
    const float* W1or = (const float*)d_in[map[8]];
    const float* b1r  = (const float*)d_in[map[9]];
    const float* W2g  = (const float*)d_in[map[10]];
    const float* b2g  = (const float*)d_in[map[11]];
    const float* W2ri = (const float*)d_in[map[12]];
    const float* W2oi = (const float*)d_in[map[13]];
    const float* b2i  = (const float*)d_in[map[14]];
    const float* W2rr = (const float*)d_in[map[15]];
    const float* W2or = (const float*)d_in[map[16]];
    const float* b2r  = (const float*)d_in[map[17]];
    const int* csrc = (const int*)d_in[map[18]];
    const int* cdst = (const int*)d_in[map[19]];
    const int* isrc = (const int*)d_in[map[20]];
    const int* idst = (const int*)d_in[map[21]];
    const int* rsrc = (const int*)d_in[map[22]];
    const int* rdst = (const int*)d_in[map[23]];
    float* out = (float*)d_out;

    // ---- graph prep: degree + dis + CSR (shared by both layers) ----
    k_zero_init<<<(NP + 255) / 256, 256>>>(P.deg, P.cursor, P.aggl1, P.aggl2);
    k_count<<<2048, 256>>>(cdst, P.deg);
    k_dis<<<(NP + 255) / 256, 256>>>(P.deg, P.dis);
    k_scan1<<<98, 1024>>>(P.deg, P.rowptr, P.bsum);
    k_scan2<<<1, 32>>>(P.bsum, 98);
    k_scan3<<<98, 1024>>>(P.rowptr, P.bsum);
    k_fill<<<2048, 256>>>(csrc, cdst, P.rowptr, P.cursor, P.col);

    // ---- layer 1, paper side ----
    sgemm<128, 64, 16, 8, 4><<<dim3(782, 2), 256>>>(xp, W1g, P.y, NP, HID, FP);
    sgemm<128, 64, 16, 8, 4><<<dim3(782, 2), 256>>>(xp, W1or, P.z, NP, HID, FP);
    k_r1<<<(NL * HID + 255) / 256, 256>>>(xl, W1rr, P.r1);
    k_rev<128><<<1024, 256>>>(P.r1, rsrc, rdst, P.z);
    k_final1<<<12500, 256>>>(P.rowptr, P.col, P.dis, P.y, P.z, b1g, b1r, P.xp1);

    // ---- layer 1, label side ----
    k_is<<<1024, 256>>>(xp, isrc, idst, P.aggl1);
    k_label1a<<<(NL * HID + 255) / 256, 256>>>(P.aggl1, xl, W1ri, W1oi, b1i, P.xl1);
    k_label1b<<<(NL * ED + 255) / 256, 256>>>(P.xl1, W2rr, W2oi, b2i, P.r2, P.t2);

    // ---- layer 2, paper side ----
    sgemm<128, 64, 16, 8, 4><<<dim3(782, 1), 256>>>(P.xp1, W2g, P.y, NP, ED, HID);
    sgemm<128, 64, 16, 8, 4><<<dim3(782, 1), 256>>>(P.xp1, W2or, P.z, NP, ED, HID);
    k_rev<64><<<1024, 256>>>(P.r2, rsrc, rdst, P.z);
    k_final2<<<12500, 256>>>(P.rowptr, P.col, P.dis, P.y, P.z, b2g, b2r, out);

    // ---- layer 2, label side ----
    k_is<<<1024, 256>>>(P.xp1, isrc, idst, P.aggl2);
    if (out_size >= NP * ED + NL * ED)
        k_label2<<<(NL * ED + 255) / 256, 256>>>(P.aggl2, P.t2, W2ri, out + (size_t)NP * ED);
}

// round 15
// speedup vs baseline: 1.7547x; 1.0185x over previous
#include <cuda_runtime.h>

#define NP 100000
#define NL 64
#define FP 128
#define FL 64
#define HID 128
#define ED 64
#define EC 1600000
#define EI 100000
#define ER 100000

// ---------------- scratch (device globals; no allocations) -------------------
__device__ int   g_deg[NP];
__device__ int   g_cursor[NP];
__device__ int   g_rowptr[NP + 1];
__device__ int   g_col[EC];
__device__ int   g_bsum[128];
__device__ float g_dis[NP];
__device__ float g_y[NP * HID];
__device__ float g_z[NP * HID];
__device__ float g_xp1[NP * HID];
__device__ float g_r1[NL * HID];
__device__ float g_r2[NL * ED];
__device__ float g_t2[NL * ED];
__device__ float g_xl1[NL * HID];
__device__ float g_aggl1[NL * HID];
__device__ float g_aggl2[NL * HID];

__device__ __forceinline__ int clampi(int v, int hi) {
    return v < 0 ? 0 : (v >= hi ? hi - 1 : v);
}

// ---------------- init / degree / dis ----------------------------------------
__global__ void k_zero_init(int* deg, int* cursor, float* a1, float* a2) {
    int i = blockIdx.x * blockDim.x + threadIdx.x;
    if (i < NP) { deg[i] = 0; cursor[i] = 0; }
    if (i < NL * HID) { a1[i] = 0.f; a2[i] = 0.f; }
}

__global__ void k_count(const int* __restrict__ dst, int* deg) {
    for (int e = blockIdx.x * blockDim.x + threadIdx.x; e < EC;
         e += gridDim.x * blockDim.x)
        atomicAdd(&deg[clampi(dst[e], NP)], 1);
}

__global__ void k_dis(const int* __restrict__ deg, float* dis) {
    int i = blockIdx.x * blockDim.x + threadIdx.x;
    if (i < NP) dis[i] = rsqrtf((float)(deg[i] + 1));
}

// ---------------- exclusive scan of degrees -> rowptr -------------------------
__global__ void k_scan1(const int* __restrict__ deg, int* rowptr, int* bsum) {
    __shared__ int s[1024];
    int t = threadIdx.x;
    int idx = blockIdx.x * 1024 + t;
    int v = (idx < NP) ? deg[idx] : 0;
    s[t] = v;
    __syncthreads();
    for (int off = 1; off < 1024; off <<= 1) {
        int x = (t >= off) ? s[t - off] : 0;
        __syncthreads();
        s[t] += x;
        __syncthreads();
    }
    if (idx < NP) rowptr[idx + 1] = s[t];
    if (t == 1023) bsum[blockIdx.x] = s[1023];
}

__global__ void k_scan2(int* bsum, int nb) {
    if (threadIdx.x == 0 && blockIdx.x == 0) {
        int run = 0;
        for (int b = 0; b < nb; b++) { int x = bsum[b]; bsum[b] = run; run += x; }
    }
}

__global__ void k_scan3(int* rowptr, const int* __restrict__ bsum) {
    int t = threadIdx.x;
    int idx = blockIdx.x * 1024 + t;
    if (idx < NP) rowptr[idx + 1] += bsum[blockIdx.x];
    if (idx == 0) rowptr[0] = 0;
}

__global__ void k_fill(const int* __restrict__ src, const int* __restrict__ dst,
                       const int* __restrict__ rowptr, int* cursor, int* col) {
    for (int e = blockIdx.x * blockDim.x + threadIdx.x; e < EC;
         e += gridDim.x * blockDim.x) {
        int d = clampi(dst[e], NP);
        int p = atomicAdd(&cursor[d], 1);
        col[clampi(rowptr[d] + p, EC)] = clampi(src[e], NP);
    }
}

// ------- fused dual-output SGEMM: C1 = A@W1, C2 = A@W2 (shared A tile) -------
// BM=128, BN=64 per output, BK=16, TM=8, TN=4 per output, 256 threads.
// Per k-step: 4 LDS.128 feed 64 FFMA (vs 3:32 in the single-output version).
__global__ void sgemm2(const float* __restrict__ A,
                       const float* __restrict__ W1, const float* __restrict__ W2,
                       float* __restrict__ C1, float* __restrict__ C2,
                       int M, int N, int K) {
    const int BM = 128, BN = 64, BK = 16;
    __shared__ float As[BK][BM];
    __shared__ float Bs1[BK][BN];
    __shared__ float Bs2[BK][BN];
    const int tx = threadIdx.x % 16; // 0..15 -> N
    const int ty = threadIdx.x / 16; // 0..15 -> M
    const int m0 = blockIdx.x * BM;
    const int n0 = blockIdx.y * BN;

    float acc1[8][4], acc2[8][4];
#pragma unroll
    for (int i = 0; i < 8; i++)
#pragma unroll
        for (int j = 0; j < 4; j++) { acc1[i][j] = 0.f; acc2[i][j] = 0.f; }

    for (int k0 = 0; k0 < K; k0 += BK) {
        // A tile (BM x BK): 512 float4, 2 per thread
#pragma unroll
        for (int u = 0; u < 2; u++) {
            int idx4 = threadIdx.x + u * 256;
            int r = idx4 / 4;
            int c = (idx4 % 4) * 4;
            int gm = m0 + r;
            float4 v = make_float4(0.f, 0.f, 0.f, 0.f);
            if (gm < M) v = *(const float4*)&A[(size_t)gm * K + k0 + c];
            As[c + 0][r] = v.x;
            As[c + 1][r] = v.y;
            As[c + 2][r] = v.z;
            As[c + 3][r] = v.w;
        }
        // B tiles (BK x BN): 256 float4 each, 1 per thread per tile
        {
            int r = threadIdx.x / 16;
            int c = (threadIdx.x % 16) * 4;
            *(float4*)&Bs1[r][c] = *(const float4*)&W1[(size_t)(k0 + r) * N + n0 + c];
            *(float4*)&Bs2[r][c] = *(const float4*)&W2[(size_t)(k0 + r) * N + n0 + c];
        }
        __syncthreads();
#pragma unroll
        for (int k = 0; k < BK; k++) {
            float4 a0 = *(const float4*)&As[k][ty * 8];
            float4 a1 = *(const float4*)&As[k][ty * 8 + 4];
            float4 b1 = *(const float4*)&Bs1[k][tx * 4];
            float4 b2 = *(const float4*)&Bs2[k][tx * 4];
            float ra[8] = {a0.x, a0.y, a0.z, a0.w, a1.x, a1.y, a1.z, a1.w};
            float rb1[4] = {b1.x, b1.y, b1.z, b1.w};
            float rb2[4] = {b2.x, b2.y, b2.z, b2.w};
#pragma unroll
            for (int i = 0; i < 8; i++)
#pragma unroll
                for (int j = 0; j < 4; j++) {
                    acc1[i][j] += ra[i] * rb1[j];
                    acc2[i][j] += ra[i] * rb2[j];
                }
        }
        __syncthreads();
    }
#pragma unroll
    for (int i = 0; i < 8; i++) {
        int gm = m0 + ty * 8 + i;
        if (gm < M) {
            *(float4*)&C1[(size_t)gm * N + n0 + tx * 4] =
                make_float4(acc1[i][0], acc1[i][1], acc1[i][2], acc1[i][3]);
            *(float4*)&C2[(size_t)gm * N + n0 + tx * 4] =
                make_float4(acc2[i][0], acc2[i][1], acc2[i][2], acc2[i][3]);
        }
    }
}

// ---------------- tiny GEMM: r1 = xl @ W1rr  (64x64 @ 64x128) ----------------
__global__ void k_r1(const float* __restrict__ xl, const float* __restrict__ W,
                     float* __restrict__ r1) {
    int o = blockIdx.x * blockDim.x + threadIdx.x;
    if (o >= NL * HID) return;
    int i = o >> 7, j = o & 127;
    float acc = 0.f;
    for (int k = 0; k < FL; k++) acc += __ldg(&xl[i * FL + k]) * __ldg(&W[k * HID + j]);
    r1[o] = acc;
}

// ---------------- rev scatter: Z[dst] += R[src] (R over NL rows) -------------
template <int C>
__global__ void k_rev(const float* __restrict__ R, const int* __restrict__ src,
                      const int* __restrict__ dst, float* __restrict__ Z) {
    int gw = (blockIdx.x * blockDim.x + threadIdx.x) >> 5;
    int lane = threadIdx.x & 31;
    int nw = (gridDim.x * blockDim.x) >> 5;
    for (int e = gw; e < ER; e += nw) {
        int s = clampi(src[e], NL), d = clampi(dst[e], NP);
        if (C == 128) {
            float4 v = ((const float4*)R)[s * 32 + lane];
            float* p = Z + (size_t)d * 128 + lane * 4;
            atomicAdd(p + 0, v.x);
            atomicAdd(p + 1, v.y);
            atomicAdd(p + 2, v.z);
            atomicAdd(p + 3, v.w);
        } else {
            float2 v = ((const float2*)R)[s * 32 + lane];
            float* p = Z + (size_t)d * 64 + lane * 2;
            atomicAdd(p + 0, v.x);
            atomicAdd(p + 1, v.y);
        }
    }
}

// ---------------- is scatter: G[dst] += X[src] (128 cols) --------------------
__global__ void k_is(const float* __restrict__ X, const int* __restrict__ src,
                     const int* __restrict__ dst, float* __restrict__ G) {
    int gw = (blockIdx.x * blockDim.x + threadIdx.x) >> 5;
    int lane = threadIdx.x & 31;
    int nw = (gridDim.x * blockDim.x) >> 5;
    for (int e = gw; e < EI; e += nw) {
        int s = clampi(src[e], NP), d = clampi(dst[e], NL);
        float4 v = ((const float4*)X)[(size_t)s * 32 + lane];
        float* p = G + (size_t)d * 128 + lane * 4;
        atomicAdd(p + 0, v.x);
        atomicAdd(p + 1, v.y);
        atomicAdd(p + 2, v.z);
        atomicAdd(p + 3, v.w);
    }
}

// ---------------- cites CSR-gather + fused epilogue (layer 1, 128 cols) ------
__global__ void k_final1(const int* __restrict__ rowptr, const int* __restrict__ col,
                         const float* __restrict__ dis, const float* __restrict__ y,
                         const float* __restrict__ z,
                         const float* __restrict__ b1g, const float* __restrict__ b1r,
                         float* __restrict__ xp1) {
    int w = (blockIdx.x * blockDim.x + threadIdx.x) >> 5;
    if (w >= NP) return;
    int lane = threadIdx.x & 31;
    int beg = rowptr[w], end = rowptr[w + 1];
    const float4* y4 = (const float4*)y;
    float4 acc = make_float4(0.f, 0.f, 0.f, 0.f);
    int e = beg;
    for (; e + 1 < end; e += 2) {   // 2-way unroll: two independent load chains
        int s0 = col[e], s1 = col[e + 1];
        float w0 = dis[s0], w1 = dis[s1];
        float4 v0 = y4[(size_t)s0 * 32 + lane];
        float4 v1 = y4[(size_t)s1 * 32 + lane];
        acc.x += w0 * v0.x + w1 * v1.x;
        acc.y += w0 * v0.y + w1 * v1.y;
        acc.z += w0 * v0.z + w1 * v1.z;
        acc.w += w0 * v0.w + w1 * v1.w;
    }
    if (e < end) {
        int s = col[e];
        float ws = dis[s];
        float4 v = y4[(size_t)s * 32 + lane];
        acc.x += ws * v.x; acc.y += ws * v.y; acc.z += ws * v.z; acc.w += ws * v.w;
    }
    float di = dis[w], d2 = di * di;
    float4 yv = y4[(size_t)w * 32 + lane];
    float4 zv = ((const float4*)z)[(size_t)w * 32 + lane];
    float4 bg = ((const float4*)b1g)[lane];
    float4 br = ((const float4*)b1r)[lane];
    float4 o;
    o.x = fmaxf(0.5f * (di * acc.x + d2 * yv.x + bg.x + zv.x + br.x), 0.f);
    o.y = fmaxf(0.5f * (di * acc.y + d2 * yv.y + bg.y + zv.y + br.y), 0.f);
    o.z = fmaxf(0.5f * (di * acc.z + d2 * yv.z + bg.z + zv.z + br.z), 0.f);
    o.w = fmaxf(0.5f * (di * acc.w + d2 * yv.w + bg.w + zv.w + br.w), 0.f);
    ((float4*)xp1)[(size_t)w * 32 + lane] = o;
}

// ---------------- cites CSR-gather + fused epilogue (layer 2, 64 cols) -------
__global__ void k_final2(const int* __restrict__ rowptr, const int* __restrict__ col,
                         const float* __restrict__ dis, const float* __restrict__ y,
                         const float* __restrict__ z,
                         const float* __restrict__ b2g, const float* __restrict__ b2r,
                         float* __restrict__ out) {
    int w = (blockIdx.x * blockDim.x + threadIdx.x) >> 5;
    if (w >= NP) return;
    int lane = threadIdx.x & 31;
    int beg = rowptr[w], end = rowptr[w + 1];
    const float2* y2 = (const float2*)y;
    float2 acc = make_float2(0.f, 0.f);
    int e = beg;
    for (; e + 1 < end; e += 2) {
        int s0 = col[e], s1 = col[e + 1];
        float w0 = dis[s0], w1 = dis[s1];
        float2 v0 = y2[(size_t)s0 * 32 + lane];
        float2 v1 = y2[(size_t)s1 * 32 + lane];
        acc.x += w0 * v0.x + w1 * v1.x;
        acc.y += w0 * v0.y + w1 * v1.y;
    }
    if (e < end) {
        int s = col[e];
        float ws = dis[s];
        float2 v = y2[(size_t)s * 32 + lane];
        acc.x += ws * v.x; acc.y += ws * v.y;
    }
    float di = dis[w], d2 = di * di;
    float2 yv = y2[(size_t)w * 32 + lane];
    float2 zv = ((const float2*)z)[(size_t)w * 32 + lane];
    float2 bg = ((const float2*)b2g)[lane];
    float2 br = ((const float2*)b2r)[lane];
    float2 o;
    o.x = 0.5f * (di * acc.x + d2 * yv.x + bg.x + zv.x + br.x);
    o.y = 0.5f * (di * acc.y + d2 * yv.y + bg.y + zv.y + br.y);
    ((float2*)out)[(size_t)w * 32 + lane] = o;
}

// ---------------- label layer 1: xl1 = relu(aggl1@W1ri + xl@W1oi + b1i) ------
__global__ void k_label1a(const float* __restrict__ aggl1, const float* __restrict__ xl,
                          const float* __restrict__ W1ri, const float* __restrict__ W1oi,
                          const float* __restrict__ b1i, float* __restrict__ xl1) {
    int o = blockIdx.x * blockDim.x + threadIdx.x;
    if (o >= NL * HID) return;
    int i = o >> 7, j = o & 127;
    float acc = __ldg(&b1i[j]);
    for (int k = 0; k < HID; k++)
        acc += aggl1[i * HID + k] * __ldg(&W1ri[k * HID + j]);
    for (int k = 0; k < FL; k++)
        acc += __ldg(&xl[i * FL + k]) * __ldg(&W1oi[k * HID + j]);
    xl1[o] = fmaxf(acc, 0.f);
}

// ---------------- label pre-transforms: r2 = xl1@W2rr, t2 = xl1@W2oi + b2i ---
__global__ void k_label1b(const float* __restrict__ xl1, const float* __restrict__ W2rr,
                          const float* __restrict__ W2oi, const float* __restrict__ b2i,
                          float* __restrict__ r2, float* __restrict__ t2) {
    int o = blockIdx.x * blockDim.x + threadIdx.x;
    if (o >= NL * ED) return;
    int i = o >> 6, j = o & 63;
    float a1 = 0.f, a2 = __ldg(&b2i[j]);
    for (int k = 0; k < HID; k++) {
        float xv = xl1[i * HID + k];
        a1 += xv * __ldg(&W2rr[k * ED + j]);
        a2 += xv * __ldg(&W2oi[k * ED + j]);
    }
    r2[o] = a1;
    t2[o] = a2;
}

// ---------------- label layer 2: out_l = aggl2@W2ri + t2 ---------------------
__global__ void k_label2(const float* __restrict__ aggl2, const float* __restrict__ t2,
                         const float* __restrict__ W2ri, float* __restrict__ out) {
    int o = blockIdx.x * blockDim.x + threadIdx.x;
    if (o >= NL * ED) return;
    int i = o >> 6, j = o & 63;
    float acc = t2[o];
    for (int k = 0; k < HID; k++)
        acc += aggl2[i * HID + k] * __ldg(&W2ri[k * ED + j]);
    out[o] = acc;
}

// ---------------- launch -----------------------------------------------------
static const long long SIG_INS[24] = {
    12800000, 4096, 16384, 128, 16384, 8192, 128, 8192, 16384, 128,
    8192, 64, 8192, 8192, 64, 8192, 8192, 64,
    1600000, 1600000, 100000, 100000, 100000, 100000};
static const long long SIG_ALPHA[24] = {
    16384, 8192, 16384, 16384, 8192, 8192, 8192, 8192, 8192, 8192,
    128, 128, 128, 64, 64, 64,
    1600000, 1600000, 100000, 100000, 100000, 100000, 4096, 12800000};
static const int MAP_ALPHA[24] = {
    23, 22, 0, 10, 3, 1, 11, 4, 2, 12, 5, 13, 8, 6, 14, 9, 7, 15,
    17, 16, 19, 18, 21, 20};

static bool sig_match(const int* sz, const long long* sig, long long scale) {
    for (int i = 0; i < 24; i++)
        if ((long long)sz[i] != sig[i] * scale) return false;
    return true;
}

struct Scratch {
    int *deg, *cursor, *rowptr, *col, *bsum;
    float *dis, *y, *z, *xp1, *r1, *r2, *t2, *xl1, *aggl1, *aggl2;
};
static Scratch P = {};

static void resolve_scratch() {
    if (P.deg) return;
    cudaGetSymbolAddress((void**)&P.deg,    g_deg);
    cudaGetSymbolAddress((void**)&P.cursor, g_cursor);
    cudaGetSymbolAddress((void**)&P.rowptr, g_rowptr);
    cudaGetSymbolAddress((void**)&P.col,    g_col);
    cudaGetSymbolAddress((void**)&P.bsum,   g_bsum);
    cudaGetSymbolAddress((void**)&P.dis,    g_dis);
    cudaGetSymbolAddress((void**)&P.y,      g_y);
    cudaGetSymbolAddress((void**)&P.z,      g_z);
    cudaGetSymbolAddress((void**)&P.xp1,    g_xp1);
    cudaGetSymbolAddress((void**)&P.r1,     g_r1);
    cudaGetSymbolAddress((void**)&P.r2,     g_r2);
    cudaGetSymbolAddress((void**)&P.t2,     g_t2);
    cudaGetSymbolAddress((void**)&P.xl1,    g_xl1);
    cudaGetSymbolAddress((void**)&P.aggl1,  g_aggl1);
    cudaGetSymbolAddress((void**)&P.aggl2,  g_aggl2);
}

extern "C" void kernel_launch(void* const* d_in, const int* in_sizes, int n_in,
                              void* d_out, int out_size) {
    resolve_scratch();

    int map[24];
    for (int i = 0; i < 24; i++) map[i] = i;
    if (n_in >= 24) {
        if (sig_match(in_sizes, SIG_INS, 1) || sig_match(in_sizes, SIG_INS, 4)) {
        } else if (sig_match(in_sizes, SIG_ALPHA, 1) ||
                   sig_match(in_sizes, SIG_ALPHA, 4)) {
            for (int i = 0; i < 24; i++) map[i] = MAP_ALPHA[i];
        } else if (in_sizes[23] == 12800000 || in_sizes[23] == 51200000) {
            for (int i = 0; i < 24; i++) map[i] = MAP_ALPHA[i];
        }
    }

    const float* xp   = (const float*)d_in[map[0]];
    const float* xl   = (const float*)d_in[map[1]];
    const float* W1g  = (const float*)d_in[map[2]];
    const float* b1g  = (const float*)d_in[map[3]];
    const float* W1ri = (const float*)d_in[map[4]];
    const float* W1oi = (const float*)d_in[map[5]];
    const float* b1i  = (const float*)d_in[map[6]];
    const float* W1rr = (const float*)d_in[map[7]];
    const float* W1or = (const float*)d_in[map[8]];
    const float* b1r  = (const float*)d_in[map[9]];
    const float* W2g  = (const float*)d_in[map[10]];
    const float* b2g  = (const float*)d_in[map[11]];
    const float* W2ri = (const float*)d_in[map[12]];
    const float* W2oi = (const float*)d_in[map[13]];
    const float* b2i  = (const float*)d_in[map[14]];
    const float* W2rr = (const float*)d_in[map[15]];
    const float* W2or = (const float*)d_in[map[16]];
    const float* b2r  = (const float*)d_in[map[17]];
    const int* csrc = (const int*)d_in[map[18]];
    const int* cdst = (const int*)d_in[map[19]];
    const int* isrc = (const int*)d_in[map[20]];
    const int* idst = (const int*)d_in[map[21]];
    const int* rsrc = (const int*)d_in[map[22]];
    const int* rdst = (const int*)d_in[map[23]];
    float* out = (float*)d_out;

    // ---- graph prep: degree + dis + CSR (shared by both layers) ----
    k_zero_init<<<(NP + 255) / 256, 256>>>(P.deg, P.cursor, P.aggl1, P.aggl2);
    k_count<<<2048, 256>>>(cdst, P.deg);
    k_dis<<<(NP + 255) / 256, 256>>>(P.deg, P.dis);
    k_scan1<<<98, 1024>>>(P.deg, P.rowptr, P.bsum);
    k_scan2<<<1, 32>>>(P.bsum, 98);
    k_scan3<<<98, 1024>>>(P.rowptr, P.bsum);
    k_fill<<<2048, 256>>>(csrc, cdst, P.rowptr, P.cursor, P.col);

    // ---- layer 1, paper side (fused dual GEMM: y = xp@W1g, z = xp@W1or) ----
    sgemm2<<<dim3(782, 2), 256>>>(xp, W1g, W1or, P.y, P.z, NP, HID, FP);
    k_r1<<<(NL * HID + 255) / 256, 256>>>(xl, W1rr, P.r1);
    k_rev<128><<<1024, 256>>>(P.r1, rsrc, rdst, P.z);
    k_final1<<<12500, 256>>>(P.rowptr, P.col, P.dis, P.y, P.z, b1g, b1r, P.xp1);

    // ---- layer 1, label side ----
    k_is<<<1024, 256>>>(xp, isrc, idst, P.aggl1);
    k_label1a<<<(NL * HID + 255) / 256, 256>>>(P.aggl1, xl, W1ri, W1oi, b1i, P.xl1);
    k_label1b<<<(NL * ED + 255) / 256, 256>>>(P.xl1, W2rr, W2oi, b2i, P.r2, P.t2);

    // ---- layer 2, paper side (fused dual GEMM) ----
    sgemm2<<<dim3(782, 1), 256>>>(P.xp1, W2g, W2or, P.y, P.z, NP, ED, HID);
    k_rev<64><<<1024, 256>>>(P.r2, rsrc, rdst, P.z);
    k_final2<<<12500, 256>>>(P.rowptr, P.col, P.dis, P.y, P.z, b2g, b2r, out);

    // ---- layer 2, label side ----
    k_is<<<1024, 256>>>(P.xp1, isrc, idst, P.aggl2);
    if (out_size >= NP * ED + NL * ED)
        k_label2<<<(NL * ED + 255) / 256, 256>>>(P.aggl2, P.t2, W2ri, out + (size_t)NP * ED);
}

// round 17
// speedup vs baseline: 1.7577x; 1.0017x over previous
#include <cuda_runtime.h>

#define NP 100000
#define NL 64
#define FP 128
#define FL 64
#define HID 128
#define ED 64
#define EC 1600000
#define EI 100000
#define ER 100000

// ---------------- scratch (device globals; no allocations) -------------------
__device__ int   g_deg[NP];
__device__ int   g_cursor[NP];
__device__ int   g_rowptr[NP + 1];
__device__ int   g_col[EC];
__device__ int   g_bsum[128];
__device__ float g_dis[NP];
__device__ float g_y[NP * HID];   // dis-scaled GCN transform (ys)
__device__ float g_z[NP * HID];
__device__ float g_xp1[NP * HID];
__device__ float g_r1[NL * HID];
__device__ float g_r2[NL * ED];
__device__ float g_t2[NL * ED];
__device__ float g_xl1[NL * HID];
__device__ float g_aggl1[NL * HID];
__device__ float g_aggl2[NL * HID];

__device__ __forceinline__ int clampi(int v, int hi) {
    return v < 0 ? 0 : (v >= hi ? hi - 1 : v);
}

// ---------------- init / degree / dis ----------------------------------------
__global__ void k_zero_init(int* deg, int* cursor, float* a1, float* a2) {
    int i = blockIdx.x * blockDim.x + threadIdx.x;
    if (i < NP) { deg[i] = 0; cursor[i] = 0; }
    if (i < NL * HID) { a1[i] = 0.f; a2[i] = 0.f; }
}

__global__ void k_count(const int* __restrict__ dst, int* deg) {
    for (int e = blockIdx.x * blockDim.x + threadIdx.x; e < EC;
         e += gridDim.x * blockDim.x)
        atomicAdd(&deg[clampi(dst[e], NP)], 1);
}

__global__ void k_dis(const int* __restrict__ deg, float* dis) {
    int i = blockIdx.x * blockDim.x + threadIdx.x;
    if (i < NP) dis[i] = rsqrtf((float)(deg[i] + 1));
}

// ---------------- exclusive scan of degrees -> rowptr -------------------------
__global__ void k_scan1(const int* __restrict__ deg, int* rowptr, int* bsum) {
    __shared__ int s[1024];
    int t = threadIdx.x;
    int idx = blockIdx.x * 1024 + t;
    int v = (idx < NP) ? deg[idx] : 0;
    s[t] = v;
    __syncthreads();
    for (int off = 1; off < 1024; off <<= 1) {
        int x = (t >= off) ? s[t - off] : 0;
        __syncthreads();
        s[t] += x;
        __syncthreads();
    }
    if (idx < NP) rowptr[idx + 1] = s[t];
    if (t == 1023) bsum[blockIdx.x] = s[1023];
}

__global__ void k_scan2(int* bsum, int nb) {
    if (threadIdx.x == 0 && blockIdx.x == 0) {
        int run = 0;
        for (int b = 0; b < nb; b++) { int x = bsum[b]; bsum[b] = run; run += x; }
    }
}

__global__ void k_scan3(int* rowptr, const int* __restrict__ bsum) {
    int t = threadIdx.x;
    int idx = blockIdx.x * 1024 + t;
    if (idx < NP) rowptr[idx + 1] += bsum[blockIdx.x];
    if (idx == 0) rowptr[0] = 0;
}

__global__ void k_fill(const int* __restrict__ src, const int* __restrict__ dst,
                       const int* __restrict__ rowptr, int* cursor, int* col) {
    for (int e = blockIdx.x * blockDim.x + threadIdx.x; e < EC;
         e += gridDim.x * blockDim.x) {
        int d = clampi(dst[e], NP);
        int p = atomicAdd(&cursor[d], 1);
        col[clampi(rowptr[d] + p, EC)] = clampi(src[e], NP);
    }
}

// ------- fused dual-output SGEMM: C1 = scale[m]*(A@W1), C2 = A@W2 ------------
// C1 is the GCN branch: scaling by dis[m] at the epilogue turns the edge
// gather into a pure unweighted row-sum (dis[s]*y[s] = ys[s]).
__global__ void sgemm2(const float* __restrict__ A,
                       const float* __restrict__ W1, const float* __restrict__ W2,
                       const float* __restrict__ scale,
                       float* __restrict__ C1, float* __restrict__ C2,
                       int M, int N, int K) {
    const int BM = 128, BN = 64, BK = 16;
    __shared__ float As[BK][BM];
    __shared__ float Bs1[BK][BN];
    __shared__ float Bs2[BK][BN];
    const int tx = threadIdx.x % 16;
    const int ty = threadIdx.x / 16;
    const int m0 = blockIdx.x * BM;
    const int n0 = blockIdx.y * BN;

    float acc1[8][4], acc2[8][4];
#pragma unroll
    for (int i = 0; i < 8; i++)
#pragma unroll
        for (int j = 0; j < 4; j++) { acc1[i][j] = 0.f; acc2[i][j] = 0.f; }

    for (int k0 = 0; k0 < K; k0 += BK) {
#pragma unroll
        for (int u = 0; u < 2; u++) {
            int idx4 = threadIdx.x + u * 256;
            int r = idx4 / 4;
            int c = (idx4 % 4) * 4;
            int gm = m0 + r;
            float4 v = make_float4(0.f, 0.f, 0.f, 0.f);
            if (gm < M) v = *(const float4*)&A[(size_t)gm * K + k0 + c];
            As[c + 0][r] = v.x;
            As[c + 1][r] = v.y;
            As[c + 2][r] = v.z;
            As[c + 3][r] = v.w;
        }
        {
            int r = threadIdx.x / 16;
            int c = (threadIdx.x % 16) * 4;
            *(float4*)&Bs1[r][c] = *(const float4*)&W1[(size_t)(k0 + r) * N + n0 + c];
            *(float4*)&Bs2[r][c] = *(const float4*)&W2[(size_t)(k0 + r) * N + n0 + c];
        }
        __syncthreads();
#pragma unroll
        for (int k = 0; k < BK; k++) {
            float4 a0 = *(const float4*)&As[k][ty * 8];
            float4 a1 = *(const float4*)&As[k][ty * 8 + 4];
            float4 b1 = *(const float4*)&Bs1[k][tx * 4];
            float4 b2 = *(const float4*)&Bs2[k][tx * 4];
            float ra[8] = {a0.x, a0.y, a0.z, a0.w, a1.x, a1.y, a1.z, a1.w};
            float rb1[4] = {b1.x, b1.y, b1.z, b1.w};
            float rb2[4] = {b2.x, b2.y, b2.z, b2.w};
#pragma unroll
            for (int i = 0; i < 8; i++)
#pragma unroll
                for (int j = 0; j < 4; j++) {
                    acc1[i][j] += ra[i] * rb1[j];
                    acc2[i][j] += ra[i] * rb2[j];
                }
        }
        __syncthreads();
    }
#pragma unroll
    for (int i = 0; i < 8; i++) {
        int gm = m0 + ty * 8 + i;
        if (gm < M) {
            float s1 = scale[gm];
            *(float4*)&C1[(size_t)gm * N + n0 + tx * 4] =
                make_float4(acc1[i][0] * s1, acc1[i][1] * s1,
                            acc1[i][2] * s1, acc1[i][3] * s1);
            *(float4*)&C2[(size_t)gm * N + n0 + tx * 4] =
                make_float4(acc2[i][0], acc2[i][1], acc2[i][2], acc2[i][3]);
        }
    }
}

// ---------------- tiny GEMM: r1 = xl @ W1rr  (64x64 @ 64x128) ----------------
__global__ void k_r1(const float* __restrict__ xl, const float* __restrict__ W,
                     float* __restrict__ r1) {
    int o = blockIdx.x * blockDim.x + threadIdx.x;
    if (o >= NL * HID) return;
    int i = o >> 7, j = o & 127;
    float acc = 0.f;
    for (int k = 0; k < FL; k++) acc += __ldg(&xl[i * FL + k]) * __ldg(&W[k * HID + j]);
    r1[o] = acc;
}

// ---------------- rev scatter: Z[dst] += R[src] (R over NL rows) -------------
template <int C>
__global__ void k_rev(const float* __restrict__ R, const int* __restrict__ src,
                      const int* __restrict__ dst, float* __restrict__ Z) {
    int gw = (blockIdx.x * blockDim.x + threadIdx.x) >> 5;
    int lane = threadIdx.x & 31;
    int nw = (gridDim.x * blockDim.x) >> 5;
    for (int e = gw; e < ER; e += nw) {
        int s = clampi(src[e], NL), d = clampi(dst[e], NP);
        if (C == 128) {
            float4 v = ((const float4*)R)[s * 32 + lane];
            float* p = Z + (size_t)d * 128 + lane * 4;
            atomicAdd(p + 0, v.x);
            atomicAdd(p + 1, v.y);
            atomicAdd(p + 2, v.z);
            atomicAdd(p + 3, v.w);
        } else {
            float2 v = ((const float2*)R)[s * 32 + lane];
            float* p = Z + (size_t)d * 64 + lane * 2;
            atomicAdd(p + 0, v.x);
            atomicAdd(p + 1, v.y);
        }
    }
}

// ---------------- is scatter: G[dst] += X[src] (128 cols) --------------------
__global__ void k_is(const float* __restrict__ X, const int* __restrict__ src,
                     const int* __restrict__ dst, float* __restrict__ G) {
    int gw = (blockIdx.x * blockDim.x + threadIdx.x) >> 5;
    int lane = threadIdx.x & 31;
    int nw = (gridDim.x * blockDim.x) >> 5;
    for (int e = gw; e < EI; e += nw) {
        int s = clampi(src[e], NP), d = clampi(dst[e], NL);
        float4 v = ((const float4*)X)[(size_t)s * 32 + lane];
        float* p = G + (size_t)d * 128 + lane * 4;
        atomicAdd(p + 0, v.x);
        atomicAdd(p + 1, v.y);
        atomicAdd(p + 2, v.z);
        atomicAdd(p + 3, v.w);
    }
}

// ---------------- cites CSR-gather + fused epilogue (layer 1, 128 cols) ------
// ys is pre-scaled by dis: acc = sum_s ys[s] + ys[w];
// out = relu(0.5*(di*acc + b1g + z + b1r))
__global__ void k_final1(const int* __restrict__ rowptr, const int* __restrict__ col,
                         const float* __restrict__ dis, const float* __restrict__ ys,
                         const float* __restrict__ z,
                         const float* __restrict__ b1g, const float* __restrict__ b1r,
                         float* __restrict__ xp1) {
    int w = (blockIdx.x * blockDim.x + threadIdx.x) >> 5;
    if (w >= NP) return;
    int lane = threadIdx.x & 31;
    int beg = rowptr[w], end = rowptr[w + 1];
    const float4* y4 = (const float4*)ys;
    float4 acc = y4[(size_t)w * 32 + lane];  // self term
    int e = beg;
    for (; e + 3 < end; e += 4) {  // 4 independent row-load chains
        int s0 = col[e], s1 = col[e + 1], s2 = col[e + 2], s3 = col[e + 3];
        float4 v0 = y4[(size_t)s0 * 32 + lane];
        float4 v1 = y4[(size_t)s1 * 32 + lane];
        float4 v2 = y4[(size_t)s2 * 32 + lane];
        float4 v3 = y4[(size_t)s3 * 32 + lane];
        acc.x += (v0.x + v1.x) + (v2.x + v3.x);
        acc.y += (v0.y + v1.y) + (v2.y + v3.y);
        acc.z += (v0.z + v1.z) + (v2.z + v3.z);
        acc.w += (v0.w + v1.w) + (v2.w + v3.w);
    }
    for (; e < end; e++) {
        float4 v = y4[(size_t)col[e] * 32 + lane];
        acc.x += v.x; acc.y += v.y; acc.z += v.z; acc.w += v.w;
    }
    float di = dis[w];
    float4 zv = ((const float4*)z)[(size_t)w * 32 + lane];
    float4 bg = ((const float4*)b1g)[lane];
    float4 br = ((const float4*)b1r)[lane];
    float4 o;
    o.x = fmaxf(0.5f * (di * acc.x + bg.x + zv.x + br.x), 0.f);
    o.y = fmaxf(0.5f * (di * acc.y + bg.y + zv.y + br.y), 0.f);
    o.z = fmaxf(0.5f * (di * acc.z + bg.z + zv.z + br.z), 0.f);
    o.w = fmaxf(0.5f * (di * acc.w + bg.w + zv.w + br.w), 0.f);
    ((float4*)xp1)[(size_t)w * 32 + lane] = o;
}

// ---------------- cites CSR-gather + fused epilogue (layer 2, 64 cols) -------
__global__ void k_final2(const int* __restrict__ rowptr, const int* __restrict__ col,
                         const float* __restrict__ dis, const float* __restrict__ ys,
                         const float* __restrict__ z,
                         const float* __restrict__ b2g, const float* __restrict__ b2r,
                         float* __restrict__ out) {
    int w = (blockIdx.x * blockDim.x + threadIdx.x) >> 5;
    if (w >= NP) return;
    int lane = threadIdx.x & 31;
    int beg = rowptr[w], end = rowptr[w + 1];
    const float2* y2 = (const float2*)ys;
    float2 acc = y2[(size_t)w * 32 + lane];  // self term
    int e = beg;
    for (; e + 3 < end; e += 4) {
        int s0 = col[e], s1 = col[e + 1], s2 = col[e + 2], s3 = col[e + 3];
        float2 v0 = y2[(size_t)s0 * 32 + lane];
        float2 v1 = y2[(size_t)s1 * 32 + lane];
        float2 v2 = y2[(size_t)s2 * 32 + lane];
        float2 v3 = y2[(size_t)s3 * 32 + lane];
        acc.x += (v0.x + v1.x) + (v2.x + v3.x);
        acc.y += (v0.y + v1.y) + (v2.y + v3.y);
    }
    for (; e < end; e++) {
        float2 v = y2[(size_t)col[e] * 32 + lane];
        acc.x += v.x; acc.y += v.y;
    }
    float di = dis[w];
    float2 zv = ((const float2*)z)[(size_t)w * 32 + lane];
    float2 bg = ((const float2*)b2g)[lane];
    float2 br = ((const float2*)b2r)[lane];
    float2 o;
    o.x = 0.5f * (di * acc.x + bg.x + zv.x + br.x);
    o.y = 0.5f * (di * acc.y + bg.y + zv.y + br.y);
    ((float2*)out)[(size_t)w * 32 + lane] = o;
}

// ---------------- label layer 1: xl1 = relu(aggl1@W1ri + xl@W1oi + b1i) ------
__global__ void k_label1a(const float* __restrict__ aggl1, const float* __restrict__ xl,
                          const float* __restrict__ W1ri, const float* __restrict__ W1oi,
                          const float* __restrict__ b1i, float* __restrict__ xl1) {
    int o = blockIdx.x * blockDim.x + threadIdx.x;
    if (o >= NL * HID) return;
    int i = o >> 7, j = o & 127;
    float acc = __ldg(&b1i[j]);
    for (int k = 0; k < HID; k++)
        acc += aggl1[i * HID + k] * __ldg(&W1ri[k * HID + j]);
    for (int k = 0; k < FL; k++)
        acc += __ldg(&xl[i * FL + k]) * __ldg(&W1oi[k * HID + j]);
    xl1[o] = fmaxf(acc, 0.f);
}

// ---------------- label pre-transforms: r2 = xl1@W2rr, t2 = xl1@W2oi + b2i ---
__global__ void k_label1b(const float* __restrict__ xl1, const float* __restrict__ W2rr,
                          const float* __restrict__ W2oi, const float* __restrict__ b2i,
                          float* __restrict__ r2, float* __restrict__ t2) {
    int o = blockIdx.x * blockDim.x + threadIdx.x;
    if (o >= NL * ED) return;
    int i = o >> 6, j = o & 63;
    float a1 = 0.f, a2 = __ldg(&b2i[j]);
    for (int k = 0; k < HID; k++) {
        float xv = xl1[i * HID + k];
        a1 += xv * __ldg(&W2rr[k * ED + j]);
        a2 += xv * __ldg(&W2oi[k * ED + j]);
    }
    r2[o] = a1;
    t2[o] = a2;
}

// ---------------- label layer 2: out_l = aggl2@W2ri + t2 ---------------------
__global__ void k_label2(const float* __restrict__ aggl2, const float* __restrict__ t2,
                         const float* __restrict__ W2ri, float* __restrict__ out) {
    int o = blockIdx.x * blockDim.x + threadIdx.x;
    if (o >= NL * ED) return;
    int i = o >> 6, j = o & 63;
    float acc = t2[o];
    for (int k = 0; k < HID; k++)
        acc += aggl2[i * HID + k] * __ldg(&W2ri[k * ED + j]);
    out[o] = acc;
}

// ---------------- launch -----------------------------------------------------
static const long long SIG_INS[24] = {
    12800000, 4096, 16384, 128, 16384, 8192, 128, 8192, 16384, 128,
    8192, 64, 8192, 8192, 64, 8192, 8192, 64,
    1600000, 1600000, 100000, 100000, 100000, 100000};
static const long long SIG_ALPHA[24] = {
    16384, 8192, 16384, 16384, 8192, 8192, 8192, 8192, 8192, 8192,
    128, 128, 128, 64, 64, 64,
    1600000, 1600000, 100000, 100000, 100000, 100000, 4096, 12800000};
static const int MAP_ALPHA[24] = {
    23, 22, 0, 10, 3, 1, 11, 4, 2, 12, 5, 13, 8, 6, 14, 9, 7, 15,
    17, 16, 19, 18, 21, 20};

static bool sig_match(const int* sz, const long long* sig, long long scale) {
    for (int i = 0; i < 24; i++)
        if ((long long)sz[i] != sig[i] * scale) return false;
    return true;
}

struct Scratch {
    int *deg, *cursor, *rowptr, *col, *bsum;
    float *dis, *y, *z, *xp1, *r1, *r2, *t2, *xl1, *aggl1, *aggl2;
};
static Scratch P = {};

static void resolve_scratch() {
    if (P.deg) return;
    cudaGetSymbolAddress((void**)&P.deg,    g_deg);
    cudaGetSymbolAddress((void**)&P.cursor, g_cursor);
    cudaGetSymbolAddress((void**)&P.rowptr, g_rowptr);
    cudaGetSymbolAddress((void**)&P.col,    g_col);
    cudaGetSymbolAddress((void**)&P.bsum,   g_bsum);
    cudaGetSymbolAddress((void**)&P.dis,    g_dis);
    cudaGetSymbolAddress((void**)&P.y,      g_y);
    cudaGetSymbolAddress((void**)&P.z,      g_z);
    cudaGetSymbolAddress((void**)&P.xp1,    g_xp1);
    cudaGetSymbolAddress((void**)&P.r1,     g_r1);
    cudaGetSymbolAddress((void**)&P.r2,     g_r2);
    cudaGetSymbolAddress((void**)&P.t2,     g_t2);
    cudaGetSymbolAddress((void**)&P.xl1,    g_xl1);
    cudaGetSymbolAddress((void**)&P.aggl1,  g_aggl1);
    cudaGetSymbolAddress((void**)&P.aggl2,  g_aggl2);
}

extern "C" void kernel_launch(void* const* d_in, const int* in_sizes, int n_in,
                              void* d_out, int out_size) {
    resolve_scratch();

    int map[24];
    for (int i = 0; i < 24; i++) map[i] = i;
    if (n_in >= 24) {
        if (sig_match(in_sizes, SIG_INS, 1) || sig_match(in_sizes, SIG_INS, 4)) {
        } else if (sig_match(in_sizes, SIG_ALPHA, 1) ||
                   sig_match(in_sizes, SIG_ALPHA, 4)) {
            for (int i = 0; i < 24; i++) map[i] = MAP_ALPHA[i];
        } else if (in_sizes[23] == 12800000 || in_sizes[23] == 51200000) {
            for (int i = 0; i < 24; i++) map[i] = MAP_ALPHA[i];
        }
    }

    const float* xp   = (const float*)d_in[map[0]];
    const float* xl   = (const float*)d_in[map[1]];
    const float* W1g  = (const float*)d_in[map[2]];
    const float* b1g  = (const float*)d_in[map[3]];
    const float* W1ri = (const float*)d_in[map[4]];
    const float* W1oi = (const float*)d_in[map[5]];
    const float* b1i  = (const float*)d_in[map[6]];
    const float* W1rr = (const float*)d_in[map[7]];
    const float* W1or = (const float*)d_in[map[8]];
    const float* b1r  = (const float*)d_in[map[9]];
    const float* W2g  = (const float*)d_in[map[10]];
    const float* b2g  = (const float*)d_in[map[11]];
    const float* W2ri = (const float*)d_in[map[12]];
    const float* W2oi = (const float*)d_in[map[13]];
    const float* b2i  = (const float*)d_in[map[14]];
    const float* W2rr = (const float*)d_in[map[15]];
    const float* W2or = (const float*)d_in[map[16]];
    const float* b2r  = (const float*)d_in[map[17]];
    const int* csrc = (const int*)d_in[map[18]];
    const int* cdst = (const int*)d_in[map[19]];
    const int* isrc = (const int*)d_in[map[20]];
    const int* idst = (const int*)d_in[map[21]];
    const int* rsrc = (const int*)d_in[map[22]];
    const int* rdst = (const int*)d_in[map[23]];
    float* out = (float*)d_out;

    // ---- graph prep (deg/dis first; GEMM early for ncu attribution) ----
    k_zero_init<<<(NP + 255) / 256, 256>>>(P.deg, P.cursor, P.aggl1, P.aggl2);
    k_count<<<2048, 256>>>(cdst, P.deg);
    k_dis<<<(NP + 255) / 256, 256>>>(P.deg, P.dis);

    // ---- layer 1 dual GEMM: y = dis*(xp@W1g), z = xp@W1or ----
    sgemm2<<<dim3(782, 2), 256>>>(xp, W1g, W1or, P.dis, P.y, P.z, NP, HID, FP);

    // ---- CSR build ----
    k_scan1<<<98, 1024>>>(P.deg, P.rowptr, P.bsum);
    k_scan2<<<1, 32>>>(P.bsum, 98);
    k_scan3<<<98, 1024>>>(P.rowptr, P.bsum);
    k_fill<<<2048, 256>>>(csrc, cdst, P.rowptr, P.cursor, P.col);

    // ---- layer 1, paper side ----
    k_r1<<<(NL * HID + 255) / 256, 256>>>(xl, W1rr, P.r1);
    k_rev<128><<<1024, 256>>>(P.r1, rsrc, rdst, P.z);
    k_final1<<<12500, 256>>>(P.rowptr, P.col, P.dis, P.y, P.z, b1g, b1r, P.xp1);

    // ---- layer 1, label side ----
    k_is<<<1024, 256>>>(xp, isrc, idst, P.aggl1);
    k_label1a<<<(NL * HID + 255) / 256, 256>>>(P.aggl1, xl, W1ri, W1oi, b1i, P.xl1);
    k_label1b<<<(NL * ED + 255) / 256, 256>>>(P.xl1, W2rr, W2oi, b2i, P.r2, P.t2);

    // ---- layer 2, paper side ----
    sgemm2<<<dim3(782, 1), 256>>>(P.xp1, W2g, W2or, P.dis, P.y, P.z, NP, ED, HID);
    k_rev<64><<<1024, 256>>>(P.r2, rsrc, rdst, P.z);
    k_final2<<<12500, 256>>>(P.rowptr, P.col, P.dis, P.y, P.z, b2g, b2r, out);

    // ---- layer 2, label side ----
    k_is<<<1024, 256>>>(P.xp1, isrc, idst, P.aggl2);
    if (out_size >= NP * ED + NL * ED)
        k_label2<<<(NL * ED + 255) / 256, 256>>>(P.aggl2, P.t2, W2ri, out + (size_t)NP * ED);
}